// round 6
// baseline (speedup 1.0000x reference)
#include <cuda_runtime.h>
#include <cuda_fp16.h>
#include <math.h>
#include <stdint.h>

#define HDIM  1024
#define IDIM  2816
#define TWOI  5632
#define NEXP  8
#define NTOK  2048
#define NGRP  9   // 8 experts + base (group 8)

#define AS_STRIDE 20            // half2 words per row: 16 data + 4 pad (conflict-free frags)
#define A_BUF (128 * AS_STRIDE) // uint32 words per A buffer (128 rows x 32 k)
#define B_BUF (128 * AS_STRIDE) // uint32 words per B buffer (128 cols x 32 k)
#define SMEM_BYTES ((2 * A_BUF + 2 * B_BUF) * 4)   // 40960 B -> 2 CTAs/SM

// ---------------- scratch (device globals; no allocation) ----------------
__device__ int    g_cnt[NGRP];
__device__ int    g_tok[NGRP * NTOK];
__device__ int    g_te[NTOK * 2];
__device__ int    g_tp[NTOK * 2];
__device__ float  g_tw[NTOK * 2];
__device__ __half g_act[(size_t)NGRP * NTOK * IDIM];
__device__ float  g_y  [(size_t)NGRP * NTOK * HDIM];

#define MMA_F16(C, A, B)                                                      \
    asm volatile(                                                             \
        "mma.sync.aligned.m16n8k16.row.col.f32.f16.f16.f32 "                  \
        "{%0,%1,%2,%3}, {%4,%5,%6,%7}, {%8,%9}, {%0,%1,%2,%3};"               \
        : "+f"((C)[0]), "+f"((C)[1]), "+f"((C)[2]), "+f"((C)[3])              \
        : "r"((A)[0]), "r"((A)[1]), "r"((A)[2]), "r"((A)[3]),                 \
          "r"((B)[0]), "r"((B)[1]))

__device__ __forceinline__ uint32_t h2u(__half2 h) { return *(uint32_t*)&h; }

// ---------------- init ----------------
__global__ void k_init() {
    if (threadIdx.x < NGRP)
        g_cnt[threadIdx.x] = (threadIdx.x == NEXP) ? NTOK : 0;
}

// ---------------- router: warp per token ----------------
__global__ void k_router(const float* __restrict__ x, const float* __restrict__ gw) {
    int gtid = blockIdx.x * blockDim.x + threadIdx.x;
    int t    = gtid >> 5;
    int lane = gtid & 31;
    if (t >= NTOK) return;

    const float* xr = x + (size_t)t * HDIM;
    float acc[NEXP];
#pragma unroll
    for (int e = 0; e < NEXP; e++) acc[e] = 0.f;
    for (int k = lane; k < HDIM; k += 32) {
        float xv = xr[k];
        const float4* gr = (const float4*)(gw + (size_t)k * NEXP);
        float4 g0 = gr[0], g1 = gr[1];
        acc[0] += xv * g0.x; acc[1] += xv * g0.y;
        acc[2] += xv * g0.z; acc[3] += xv * g0.w;
        acc[4] += xv * g1.x; acc[5] += xv * g1.y;
        acc[6] += xv * g1.z; acc[7] += xv * g1.w;
    }
#pragma unroll
    for (int e = 0; e < NEXP; e++) {
#pragma unroll
        for (int off = 16; off; off >>= 1)
            acc[e] += __shfl_xor_sync(0xffffffffu, acc[e], off);
    }
    if (lane == 0) {
        float m = acc[0];
#pragma unroll
        for (int e = 1; e < NEXP; e++) m = fmaxf(m, acc[e]);
        float p[NEXP];
#pragma unroll
        for (int e = 0; e < NEXP; e++) p[e] = expf(acc[e] - m);
        int i0 = 0; float b0 = p[0];
#pragma unroll
        for (int e = 1; e < NEXP; e++) if (p[e] > b0) { b0 = p[e]; i0 = e; }
        int i1 = (i0 == 0) ? 1 : 0; float b1 = p[i1];
#pragma unroll
        for (int e = 0; e < NEXP; e++)
            if (e != i0 && p[e] > b1) { b1 = p[e]; i1 = e; }
        float s = b0 + b1;
        int p0 = atomicAdd(&g_cnt[i0], 1);
        int p1 = atomicAdd(&g_cnt[i1], 1);
        g_tok[i0 * NTOK + p0] = t;
        g_tok[i1 * NTOK + p1] = t;
        g_te[2 * t + 0] = i0; g_tp[2 * t + 0] = p0; g_tw[2 * t + 0] = b0 / s;
        g_te[2 * t + 1] = i1; g_tp[2 * t + 1] = p1; g_tw[2 * t + 1] = b1 / s;
        g_tok[NEXP * NTOK + t] = t;
    }
}

// ============================================================================
// GEMM1 (fp16 mma): act = silu(x@Wg) * (x@Wu)
// Block 128 rows x 64 act-cols (B tile 128 = 64 gate + 64 up).
// 8 warps 2x4: warp tile 64 rows x 32 B-cols (16 act-cols). 2 CTAs/SM.
// ============================================================================
__global__ __launch_bounds__(256, 2) void k_gemm1(const float* __restrict__ x,
                                                  const float* __restrict__ base_wgu,
                                                  const float* __restrict__ exp_wgu) {
    int g   = blockIdx.z;
    int cnt = g_cnt[g];
    int m0  = blockIdx.y * 128;
    if (m0 >= cnt) return;
    int n0  = blockIdx.x * 64;
    const float* W = (g == NEXP) ? base_wgu : (exp_wgu + (size_t)g * HDIM * TWOI);

    extern __shared__ uint32_t sm[];
    uint32_t* Abuf[2] = { sm, sm + A_BUF };
    uint32_t* Bbuf[2] = { sm + 2 * A_BUF, sm + 2 * A_BUF + B_BUF };
    __shared__ int stok[128];

    int tid = threadIdx.x, wid = tid >> 5, lane = tid & 31;
    int wm = wid & 1, wn = wid >> 1;
    int qg = lane >> 2, qq = lane & 3;

    if (tid < 128) { int r = m0 + tid; stok[tid] = g_tok[g * NTOK + ((r < cnt) ? r : cnt - 1)]; }
    __syncthreads();

    // A staging: row ar = tid>>1 (0..127), k chunk ac = tid&1 (16 floats)
    int ar = tid >> 1, ac = tid & 1;
    const float* apt = x + (size_t)stok[ar] * HDIM + ac * 16;

    // B staging: n-group ng = tid&31 (4 cols), k-quad kq = tid>>5 (0..7; pairs kq, kq+8)
    int ng = tid & 31, kq = tid >> 5;
    size_t coloff = (ng < 16) ? (size_t)(n0 + ng * 4)
                              : ((size_t)IDIM + n0 + (ng - 16) * 4);
    const float* bpt = W + (size_t)(2 * kq) * TWOI + coloff;

    float acc[4][4][4];
#pragma unroll
    for (int a = 0; a < 4; a++)
#pragma unroll
        for (int b = 0; b < 4; b++)
#pragma unroll
            for (int c = 0; c < 4; c++) acc[a][b][c] = 0.f;

    float4 ra[4];        // 16 floats of A
    float4 rb[2][2];     // 2 k-pairs x (k, k+1) rows, 4 cols each

    auto ldg_stage = [&](int kk) {
#pragma unroll
        for (int j = 0; j < 4; j++) ra[j] = *(const float4*)(apt + kk + 4 * j);
#pragma unroll
        for (int j = 0; j < 2; j++) {
            const float* p = bpt + (size_t)(kk + 16 * j) * TWOI;
            rb[j][0] = *(const float4*)(p);
            rb[j][1] = *(const float4*)(p + TWOI);
        }
    };
    auto sts_stage = [&](uint32_t* Ab, uint32_t* Bb) {
        uint32_t* aw = &Ab[ar * AS_STRIDE + ac * 8];
        aw[0] = h2u(__floats2half2_rn(ra[0].x, ra[0].y));
        aw[1] = h2u(__floats2half2_rn(ra[0].z, ra[0].w));
        aw[2] = h2u(__floats2half2_rn(ra[1].x, ra[1].y));
        aw[3] = h2u(__floats2half2_rn(ra[1].z, ra[1].w));
        aw[4] = h2u(__floats2half2_rn(ra[2].x, ra[2].y));
        aw[5] = h2u(__floats2half2_rn(ra[2].z, ra[2].w));
        aw[6] = h2u(__floats2half2_rn(ra[3].x, ra[3].y));
        aw[7] = h2u(__floats2half2_rn(ra[3].z, ra[3].w));
#pragma unroll
        for (int j = 0; j < 2; j++) {
            int kp = kq + 8 * j;
            Bb[(ng * 4 + 0) * AS_STRIDE + kp] = h2u(__floats2half2_rn(rb[j][0].x, rb[j][1].x));
            Bb[(ng * 4 + 1) * AS_STRIDE + kp] = h2u(__floats2half2_rn(rb[j][0].y, rb[j][1].y));
            Bb[(ng * 4 + 2) * AS_STRIDE + kp] = h2u(__floats2half2_rn(rb[j][0].z, rb[j][1].z));
            Bb[(ng * 4 + 3) * AS_STRIDE + kp] = h2u(__floats2half2_rn(rb[j][0].w, rb[j][1].w));
        }
    };

    ldg_stage(0);
    sts_stage(Abuf[0], Bbuf[0]);
    __syncthreads();

    const int NST = HDIM / 32;
    for (int s = 0; s < NST; s++) {
        if (s + 1 < NST) ldg_stage((s + 1) * 32);
        uint32_t* Ab = Abuf[s & 1];
        uint32_t* Bb = Bbuf[s & 1];
#pragma unroll
        for (int ks = 0; ks < 2; ks++) {
            int hb = ks * 8 + qq;
            uint32_t af[4][4], bf[4][2];
#pragma unroll
            for (int mt = 0; mt < 4; mt++) {
                int r = wm * 64 + mt * 16 + qg;
                af[mt][0] = Ab[r * AS_STRIDE + hb];
                af[mt][1] = Ab[(r + 8) * AS_STRIDE + hb];
                af[mt][2] = Ab[r * AS_STRIDE + hb + 4];
                af[mt][3] = Ab[(r + 8) * AS_STRIDE + hb + 4];
            }
#pragma unroll
            for (int nt = 0; nt < 4; nt++) {
                // nt 0,1 -> gate cols; nt 2,3 -> up cols (offset 64 in B tile)
                int c = ((nt < 2) ? (wn * 16 + 8 * nt) : (64 + wn * 16 + 8 * (nt - 2))) + qg;
                bf[nt][0] = Bb[c * AS_STRIDE + hb];
                bf[nt][1] = Bb[c * AS_STRIDE + hb + 4];
            }
#pragma unroll
            for (int mt = 0; mt < 4; mt++)
#pragma unroll
                for (int nt = 0; nt < 4; nt++)
                    MMA_F16(acc[mt][nt], af[mt], bf[nt]);
        }
        if (s + 1 < NST) sts_stage(Abuf[(s + 1) & 1], Bbuf[(s + 1) & 1]);
        __syncthreads();
    }

    // epilogue: SwiGLU (gate = acc[.][nt], up = acc[.][nt+2]), half2 stores
#pragma unroll
    for (int mt = 0; mt < 4; mt++) {
        int r0 = m0 + wm * 64 + mt * 16 + qg;
#pragma unroll
        for (int nt = 0; nt < 2; nt++) {
            int c = n0 + wn * 16 + 8 * nt + 2 * qq;
            float g0 = acc[mt][nt][0], g1 = acc[mt][nt][1];
            float u0 = acc[mt][nt + 2][0], u1 = acc[mt][nt + 2][1];
            *(__half2*)&g_act[((size_t)g * NTOK + r0) * IDIM + c] =
                __floats2half2_rn(u0 * (g0 / (1.f + expf(-g0))),
                                  u1 * (g1 / (1.f + expf(-g1))));
            float g2 = acc[mt][nt][2], g3 = acc[mt][nt][3];
            float u2 = acc[mt][nt + 2][2], u3 = acc[mt][nt + 2][3];
            *(__half2*)&g_act[((size_t)g * NTOK + r0 + 8) * IDIM + c] =
                __floats2half2_rn(u2 * (g2 / (1.f + expf(-g2))),
                                  u3 * (g3 / (1.f + expf(-g3))));
        }
    }
}

// ============================================================================
// GEMM2 (fp16 mma): y = act(half) @ Wd.  Block 128x128, warp 64x32. 2 CTAs/SM.
// ============================================================================
__global__ __launch_bounds__(256, 2) void k_gemm2(const float* __restrict__ base_wd,
                                                  const float* __restrict__ exp_wd) {
    int g   = blockIdx.z;
    int cnt = g_cnt[g];
    int m0  = blockIdx.y * 128;
    if (m0 >= cnt) return;
    int n0  = blockIdx.x * 128;
    const float* W = (g == NEXP) ? base_wd : (exp_wd + (size_t)g * IDIM * HDIM);

    extern __shared__ uint32_t sm[];
    uint32_t* Abuf[2] = { sm, sm + A_BUF };
    uint32_t* Bbuf[2] = { sm + 2 * A_BUF, sm + 2 * A_BUF + B_BUF };

    int tid = threadIdx.x, wid = tid >> 5, lane = tid & 31;
    int wm = wid & 1, wn = wid >> 1;
    int qg = lane >> 2, qq = lane & 3;

    // A staging: fp16 rows, direct copy. row ar = tid>>1, chunk ac = tid&1 (16 halves)
    int ar = tid >> 1, ac = tid & 1;
    const __half* apt = g_act + ((size_t)g * NTOK + m0 + ar) * IDIM + ac * 16;

    // B staging: ng = tid&31 (4 cols), kq = tid>>5
    int ng = tid & 31, kq = tid >> 5;
    const float* bpt = W + (size_t)(2 * kq) * HDIM + n0 + ng * 4;

    float acc[4][4][4];
#pragma unroll
    for (int a = 0; a < 4; a++)
#pragma unroll
        for (int b = 0; b < 4; b++)
#pragma unroll
            for (int c = 0; c < 4; c++) acc[a][b][c] = 0.f;

    uint4  va[2];
    float4 rb[2][2];

    auto ldg_stage = [&](int kk) {
        va[0] = *(const uint4*)(apt + kk);
        va[1] = *(const uint4*)(apt + kk + 8);
#pragma unroll
        for (int j = 0; j < 2; j++) {
            const float* p = bpt + (size_t)(kk + 16 * j) * HDIM;
            rb[j][0] = *(const float4*)(p);
            rb[j][1] = *(const float4*)(p + HDIM);
        }
    };
    auto sts_stage = [&](uint32_t* Ab, uint32_t* Bb) {
        *(uint4*)&Ab[ar * AS_STRIDE + ac * 8]     = va[0];
        *(uint4*)&Ab[ar * AS_STRIDE + ac * 8 + 4] = va[1];
#pragma unroll
        for (int j = 0; j < 2; j++) {
            int kp = kq + 8 * j;
            Bb[(ng * 4 + 0) * AS_STRIDE + kp] = h2u(__floats2half2_rn(rb[j][0].x, rb[j][1].x));
            Bb[(ng * 4 + 1) * AS_STRIDE + kp] = h2u(__floats2half2_rn(rb[j][0].y, rb[j][1].y));
            Bb[(ng * 4 + 2) * AS_STRIDE + kp] = h2u(__floats2half2_rn(rb[j][0].z, rb[j][1].z));
            Bb[(ng * 4 + 3) * AS_STRIDE + kp] = h2u(__floats2half2_rn(rb[j][0].w, rb[j][1].w));
        }
    };

    ldg_stage(0);
    sts_stage(Abuf[0], Bbuf[0]);
    __syncthreads();

    const int NST = IDIM / 32;   // 88
    for (int s = 0; s < NST; s++) {
        if (s + 1 < NST) ldg_stage((s + 1) * 32);
        uint32_t* Ab = Abuf[s & 1];
        uint32_t* Bb = Bbuf[s & 1];
#pragma unroll
        for (int ks = 0; ks < 2; ks++) {
            int hb = ks * 8 + qq;
            uint32_t af[4][4], bf[4][2];
#pragma unroll
            for (int mt = 0; mt < 4; mt++) {
                int r = wm * 64 + mt * 16 + qg;
                af[mt][0] = Ab[r * AS_STRIDE + hb];
                af[mt][1] = Ab[(r + 8) * AS_STRIDE + hb];
                af[mt][2] = Ab[r * AS_STRIDE + hb + 4];
                af[mt][3] = Ab[(r + 8) * AS_STRIDE + hb + 4];
            }
#pragma unroll
            for (int nt = 0; nt < 4; nt++) {
                int c = wn * 32 + 8 * nt + qg;
                bf[nt][0] = Bb[c * AS_STRIDE + hb];
                bf[nt][1] = Bb[c * AS_STRIDE + hb + 4];
            }
#pragma unroll
            for (int mt = 0; mt < 4; mt++)
#pragma unroll
                for (int nt = 0; nt < 4; nt++)
                    MMA_F16(acc[mt][nt], af[mt], bf[nt]);
        }
        if (s + 1 < NST) sts_stage(Abuf[(s + 1) & 1], Bbuf[(s + 1) & 1]);
        __syncthreads();
    }

#pragma unroll
    for (int mt = 0; mt < 4; mt++) {
        int r0 = m0 + wm * 64 + mt * 16 + qg;
#pragma unroll
        for (int nt = 0; nt < 4; nt++) {
            int c = n0 + wn * 32 + 8 * nt + 2 * qq;
            *(float2*)&g_y[((size_t)g * NTOK + r0) * HDIM + c] =
                make_float2(acc[mt][nt][0], acc[mt][nt][1]);
            *(float2*)&g_y[((size_t)g * NTOK + r0 + 8) * HDIM + c] =
                make_float2(acc[mt][nt][2], acc[mt][nt][3]);
        }
    }
}

// ---------------- combine ----------------
__global__ void k_combine(float* __restrict__ out) {
    int idx = blockIdx.x * blockDim.x + threadIdx.x;
    int t  = idx >> 8;
    int h4 = (idx & 255) << 2;
    if (t >= NTOK) return;

    int   e0 = g_te[2 * t + 0], p0 = g_tp[2 * t + 0];
    int   e1 = g_te[2 * t + 1], p1 = g_tp[2 * t + 1];
    float w0 = g_tw[2 * t + 0], w1 = g_tw[2 * t + 1];

    float4 yb = *(const float4*)&g_y[((size_t)NEXP * NTOK + t ) * HDIM + h4];
    float4 y0 = *(const float4*)&g_y[((size_t)e0   * NTOK + p0) * HDIM + h4];
    float4 y1 = *(const float4*)&g_y[((size_t)e1   * NTOK + p1) * HDIM + h4];

    float4 o;
    o.x = yb.x + w0 * y0.x + w1 * y1.x;
    o.y = yb.y + w0 * y0.y + w1 * y1.y;
    o.z = yb.z + w0 * y0.z + w1 * y1.z;
    o.w = yb.w + w0 * y0.w + w1 * y1.w;
    *(float4*)&out[(size_t)t * HDIM + h4] = o;
}

// ---------------- launch ----------------
extern "C" void kernel_launch(void* const* d_in, const int* in_sizes, int n_in,
                              void* d_out, int out_size) {
    const float* x        = (const float*)d_in[0];
    const float* gate_w   = (const float*)d_in[1];
    const float* base_wgu = (const float*)d_in[2];
    const float* base_wd  = (const float*)d_in[3];
    const float* exp_wgu  = (const float*)d_in[4];
    const float* exp_wd   = (const float*)d_in[5];
    float* out = (float*)d_out;

    cudaFuncSetAttribute(k_gemm1, cudaFuncAttributeMaxDynamicSharedMemorySize, SMEM_BYTES);
    cudaFuncSetAttribute(k_gemm2, cudaFuncAttributeMaxDynamicSharedMemorySize, SMEM_BYTES);

    k_init<<<1, 32>>>();
    k_router<<<(NTOK * 32) / 256, 256>>>(x, gate_w);
    k_gemm1<<<dim3(IDIM / 64, NTOK / 128, NGRP), 256, SMEM_BYTES>>>(x, base_wgu, exp_wgu);
    k_gemm2<<<dim3(HDIM / 128, NTOK / 128, NGRP), 256, SMEM_BYTES>>>(base_wd, exp_wd);
    k_combine<<<(NTOK * (HDIM / 4)) / 256, 256>>>(out);
}

// round 7
// speedup vs baseline: 2.4836x; 2.4836x over previous
#include <cuda_runtime.h>
#include <cuda_fp16.h>
#include <math.h>
#include <stdint.h>

#define HDIM  1024
#define IDIM  2816
#define TWOI  5632
#define NEXP  8
#define NTOK  2048
#define NGRP  9   // 8 experts + base (group 8)

#define STAGES 4
#define ABYTES 10240            // 128 rows x 40 halves x 2B (row stride 80B)
#define BROWB  272              // B smem row stride bytes (128 halves data + pad)
#define BBYTES (32 * BROWB)     // 8704
#define SMEM_BYTES (STAGES * (ABYTES + BBYTES))   // 75776 -> 2 CTAs/SM

// ---------------- scratch (device globals; no allocation) ----------------
__device__ int    g_cnt[NGRP];
__device__ int    g_tok[NGRP * NTOK];
__device__ int    g_te[NTOK * 2];
__device__ int    g_tp[NTOK * 2];
__device__ float  g_tw[NTOK * 2];
__device__ __half g_act[(size_t)NGRP * NTOK * IDIM];
__device__ float  g_y  [(size_t)NGRP * NTOK * HDIM];

// fp16 copies (converted once per launch; deterministic)
__device__ __half xh[NTOK * HDIM];
__device__ __half bwguh[HDIM * TWOI];
__device__ __half bwdh[IDIM * HDIM];
__device__ __half ewguh[(size_t)NEXP * HDIM * TWOI];
__device__ __half ewdh[(size_t)NEXP * IDIM * HDIM];

// ---------------- PTX helpers ----------------
__device__ __forceinline__ uint32_t h2u(__half2 h) { return *(uint32_t*)&h; }
__device__ __forceinline__ uint32_t sh_addr(const void* p) {
    return (uint32_t)__cvta_generic_to_shared(p);
}
#define MMA_F16(C, A, B)                                                      \
    asm volatile(                                                             \
        "mma.sync.aligned.m16n8k16.row.col.f32.f16.f16.f32 "                  \
        "{%0,%1,%2,%3}, {%4,%5,%6,%7}, {%8,%9}, {%0,%1,%2,%3};"               \
        : "+f"((C)[0]), "+f"((C)[1]), "+f"((C)[2]), "+f"((C)[3])              \
        : "r"((A)[0]), "r"((A)[1]), "r"((A)[2]), "r"((A)[3]),                 \
          "r"((B)[0]), "r"((B)[1]))
#define LDSM_X4(r0, r1, r2, r3, a)                                            \
    asm volatile("ldmatrix.sync.aligned.m8n8.x4.shared.b16 {%0,%1,%2,%3}, [%4];" \
                 : "=r"(r0), "=r"(r1), "=r"(r2), "=r"(r3) : "r"(a))
#define LDSM_X4T(r0, r1, r2, r3, a)                                           \
    asm volatile("ldmatrix.sync.aligned.m8n8.x4.trans.shared.b16 {%0,%1,%2,%3}, [%4];" \
                 : "=r"(r0), "=r"(r1), "=r"(r2), "=r"(r3) : "r"(a))
#define CP16(dst, src)                                                        \
    asm volatile("cp.async.cg.shared.global [%0], [%1], 16;" :: "r"(dst), "l"(src))
#define CP_COMMIT() asm volatile("cp.async.commit_group;" ::: "memory")
#define CP_WAIT2()  asm volatile("cp.async.wait_group 2;" ::: "memory")

// ---------------- init ----------------
__global__ void k_init() {
    if (threadIdx.x < NGRP)
        g_cnt[threadIdx.x] = (threadIdx.x == NEXP) ? NTOK : 0;
}

// ---------------- fp32 -> fp16 convert (x + all weights) ----------------
#define CVT_N0 (NTOK * HDIM / 8)
#define CVT_N1 (HDIM * TWOI / 8)
#define CVT_N2 (IDIM * HDIM / 8)
#define CVT_N3 (NEXP * CVT_N1)
#define CVT_N4 (NEXP * CVT_N2)
#define CVT_TOTAL ((size_t)CVT_N0 + CVT_N1 + CVT_N2 + CVT_N3 + CVT_N4)  // 9994240

__global__ void k_cvt(const float* __restrict__ x, const float* __restrict__ bwgu,
                      const float* __restrict__ bwd, const float* __restrict__ ewgu,
                      const float* __restrict__ ewd) {
    size_t i = (size_t)blockIdx.x * 256 + threadIdx.x;
    if (i >= CVT_TOTAL) return;
    const float* s; __half* d; size_t off;
    if (i < CVT_N0)                       { s = x;    d = xh;    off = i; }
    else if (i < (size_t)CVT_N0 + CVT_N1) { s = bwgu; d = bwguh; off = i - CVT_N0; }
    else if (i < (size_t)CVT_N0 + CVT_N1 + CVT_N2)
                                          { s = bwd;  d = bwdh;  off = i - CVT_N0 - CVT_N1; }
    else if (i < (size_t)CVT_N0 + CVT_N1 + CVT_N2 + CVT_N3)
                                          { s = ewgu; d = ewguh; off = i - CVT_N0 - CVT_N1 - CVT_N2; }
    else                                  { s = ewd;  d = ewdh;  off = i - CVT_N0 - CVT_N1 - CVT_N2 - (size_t)CVT_N3; }
    float4 a = ((const float4*)s)[2 * off];
    float4 b = ((const float4*)s)[2 * off + 1];
    uint4 o;
    o.x = h2u(__floats2half2_rn(a.x, a.y));
    o.y = h2u(__floats2half2_rn(a.z, a.w));
    o.z = h2u(__floats2half2_rn(b.x, b.y));
    o.w = h2u(__floats2half2_rn(b.z, b.w));
    ((uint4*)d)[off] = o;
}

// ---------------- router: warp per token ----------------
__global__ void k_router(const float* __restrict__ x, const float* __restrict__ gw) {
    int gtid = blockIdx.x * blockDim.x + threadIdx.x;
    int t    = gtid >> 5;
    int lane = gtid & 31;
    if (t >= NTOK) return;

    const float* xr = x + (size_t)t * HDIM;
    float acc[NEXP];
#pragma unroll
    for (int e = 0; e < NEXP; e++) acc[e] = 0.f;
    for (int k = lane; k < HDIM; k += 32) {
        float xv = xr[k];
        const float4* gr = (const float4*)(gw + (size_t)k * NEXP);
        float4 g0 = gr[0], g1 = gr[1];
        acc[0] += xv * g0.x; acc[1] += xv * g0.y;
        acc[2] += xv * g0.z; acc[3] += xv * g0.w;
        acc[4] += xv * g1.x; acc[5] += xv * g1.y;
        acc[6] += xv * g1.z; acc[7] += xv * g1.w;
    }
#pragma unroll
    for (int e = 0; e < NEXP; e++) {
#pragma unroll
        for (int off = 16; off; off >>= 1)
            acc[e] += __shfl_xor_sync(0xffffffffu, acc[e], off);
    }
    if (lane == 0) {
        float m = acc[0];
#pragma unroll
        for (int e = 1; e < NEXP; e++) m = fmaxf(m, acc[e]);
        float p[NEXP];
#pragma unroll
        for (int e = 0; e < NEXP; e++) p[e] = expf(acc[e] - m);
        int i0 = 0; float b0 = p[0];
#pragma unroll
        for (int e = 1; e < NEXP; e++) if (p[e] > b0) { b0 = p[e]; i0 = e; }
        int i1 = (i0 == 0) ? 1 : 0; float b1 = p[i1];
#pragma unroll
        for (int e = 0; e < NEXP; e++)
            if (e != i0 && p[e] > b1) { b1 = p[e]; i1 = e; }
        float s = b0 + b1;
        int p0 = atomicAdd(&g_cnt[i0], 1);
        int p1 = atomicAdd(&g_cnt[i1], 1);
        g_tok[i0 * NTOK + p0] = t;
        g_tok[i1 * NTOK + p1] = t;
        g_te[2 * t + 0] = i0; g_tp[2 * t + 0] = p0; g_tw[2 * t + 0] = b0 / s;
        g_te[2 * t + 1] = i1; g_tp[2 * t + 1] = p1; g_tw[2 * t + 1] = b1 / s;
        g_tok[NEXP * NTOK + t] = t;
    }
}

// ============================================================================
// GEMM1: act = silu(x@Wg) * (x@Wu). fp16 cp.async pipeline + ldmatrix + HMMA.
// Block 128 rows x 64 act-cols (B tile 128 = 64 gate + 64 up).
// 4 warps (2m x 2n), warp tile 64 x 64 B-cols. 4-stage cp.async.
// ============================================================================
__global__ __launch_bounds__(128, 2) void k_gemm1() {
    int g   = blockIdx.z;
    int cnt = g_cnt[g];
    int m0  = blockIdx.y * 128;
    if (m0 >= cnt) return;
    int n0  = blockIdx.x * 64;
    const __half* W = (g == NEXP) ? bwguh : (ewguh + (size_t)g * HDIM * TWOI);

    extern __shared__ char smraw[];
    uint32_t sb = sh_addr(smraw);
    __shared__ int stok[128];

    int tid = threadIdx.x, wid = tid >> 5, lane = tid & 31;
    int wm = wid & 1, wn = wid >> 1;
    int qg = lane >> 2, qq = lane & 3;

    { int r = m0 + tid; stok[tid] = g_tok[g * NTOK + ((r < cnt) ? r : cnt - 1)]; }
    __syncthreads();

    // cp.async mappings: A chunks c = tid + 128j -> row c>>2, quad c&3
    int arow = tid >> 2, aq = tid & 3;
    const __half* asrc[4];
#pragma unroll
    for (int j = 0; j < 4; j++)
        asrc[j] = xh + (size_t)stok[arow + 32 * j] * HDIM + aq * 8;
    uint32_t adst = (uint32_t)(arow * 80 + aq * 16);
    // B chunks: k = tid>>4 (+8j), nc = tid&15 (8 gate + 8 up chunks per k-row)
    int bk = tid >> 4, bnc = tid & 15;
    size_t bcol = (bnc < 8) ? (size_t)(n0 + bnc * 8)
                            : ((size_t)IDIM + n0 + (bnc - 8) * 8);
    const __half* bsrc = W + (size_t)bk * TWOI + bcol;
    uint32_t bdst = (uint32_t)(bk * BROWB + bnc * 16);

    // ldmatrix lane offsets
    uint32_t a_off = (uint32_t)((wm * 64 + (lane & 15)) * 80 + (lane >> 4) * 16);
    uint32_t b_off = (uint32_t)((lane & 15) * BROWB + (lane >> 4) * 16);

    float acc[4][8][4];
#pragma unroll
    for (int a = 0; a < 4; a++)
#pragma unroll
        for (int b = 0; b < 8; b++)
#pragma unroll
            for (int c = 0; c < 4; c++) acc[a][b][c] = 0.f;

    auto issue = [&](int s) {
        int kk = s * 32;
        uint32_t Ab = sb + (s & 3) * ABYTES;
        uint32_t Bb = sb + STAGES * ABYTES + (s & 3) * BBYTES;
#pragma unroll
        for (int j = 0; j < 4; j++) CP16(Ab + adst + j * (32 * 80), asrc[j] + kk);
#pragma unroll
        for (int j = 0; j < 4; j++)
            CP16(Bb + bdst + j * (8 * BROWB), bsrc + (size_t)(kk + 8 * j) * TWOI);
    };

    issue(0); CP_COMMIT();
    issue(1); CP_COMMIT();
    issue(2); CP_COMMIT();

    const int NST = HDIM / 32;   // 32
    for (int s = 0; s < NST; s++) {
        CP_WAIT2();
        __syncthreads();
        if (s + 3 < NST) issue(s + 3);
        CP_COMMIT();
        uint32_t Ab = sb + (s & 3) * ABYTES;
        uint32_t Bb = sb + STAGES * ABYTES + (s & 3) * BBYTES;
#pragma unroll
        for (int ks = 0; ks < 2; ks++) {
            uint32_t af[4][4], bf[8][2];
#pragma unroll
            for (int mt = 0; mt < 4; mt++)
                LDSM_X4(af[mt][0], af[mt][1], af[mt][2], af[mt][3],
                        Ab + a_off + mt * 1280 + ks * 32);
#pragma unroll
            for (int p = 0; p < 4; p++) {
                uint32_t na = (p < 2) ? (uint32_t)(wn * 32 + p * 16)
                                      : (uint32_t)(64 + wn * 32 + (p - 2) * 16);
                LDSM_X4T(bf[2 * p][0], bf[2 * p][1], bf[2 * p + 1][0], bf[2 * p + 1][1],
                         Bb + b_off + ks * (16 * BROWB) + na * 2);
            }
#pragma unroll
            for (int mt = 0; mt < 4; mt++)
#pragma unroll
                for (int nt = 0; nt < 8; nt++)
                    MMA_F16(acc[mt][nt], af[mt], bf[nt]);
        }
    }

    // epilogue: SwiGLU (gate = nt 0-3, up = nt 4-7 at same act cols)
#pragma unroll
    for (int mt = 0; mt < 4; mt++) {
        int r0 = m0 + wm * 64 + mt * 16 + qg;
#pragma unroll
        for (int nt = 0; nt < 4; nt++) {
            int c = n0 + wn * 32 + 8 * nt + 2 * qq;
            float gv0 = acc[mt][nt][0], gv1 = acc[mt][nt][1];
            float uv0 = acc[mt][nt + 4][0], uv1 = acc[mt][nt + 4][1];
            *(__half2*)&g_act[((size_t)g * NTOK + r0) * IDIM + c] =
                __floats2half2_rn(uv0 * (gv0 / (1.f + expf(-gv0))),
                                  uv1 * (gv1 / (1.f + expf(-gv1))));
            float gv2 = acc[mt][nt][2], gv3 = acc[mt][nt][3];
            float uv2 = acc[mt][nt + 4][2], uv3 = acc[mt][nt + 4][3];
            *(__half2*)&g_act[((size_t)g * NTOK + r0 + 8) * IDIM + c] =
                __floats2half2_rn(uv2 * (gv2 / (1.f + expf(-gv2))),
                                  uv3 * (gv3 / (1.f + expf(-gv3))));
        }
    }
}

// ============================================================================
// GEMM2: y = act(half) @ Wd. Block 128x128, 4 warps, warp 64x64. cp.async.
// ============================================================================
__global__ __launch_bounds__(128, 2) void k_gemm2() {
    int g   = blockIdx.z;
    int cnt = g_cnt[g];
    int m0  = blockIdx.y * 128;
    if (m0 >= cnt) return;
    int n0  = blockIdx.x * 128;
    const __half* W = (g == NEXP) ? bwdh : (ewdh + (size_t)g * IDIM * HDIM);

    extern __shared__ char smraw[];
    uint32_t sb = sh_addr(smraw);

    int tid = threadIdx.x, wid = tid >> 5, lane = tid & 31;
    int wm = wid & 1, wn = wid >> 1;
    int qg = lane >> 2, qq = lane & 3;

    int arow = tid >> 2, aq = tid & 3;
    const __half* asrc = g_act + ((size_t)g * NTOK + m0 + arow) * IDIM + aq * 8;
    uint32_t adst = (uint32_t)(arow * 80 + aq * 16);
    int bk = tid >> 4, bnc = tid & 15;
    const __half* bsrc = W + (size_t)bk * HDIM + n0 + bnc * 8;
    uint32_t bdst = (uint32_t)(bk * BROWB + bnc * 16);

    uint32_t a_off = (uint32_t)((wm * 64 + (lane & 15)) * 80 + (lane >> 4) * 16);
    uint32_t b_off = (uint32_t)((lane & 15) * BROWB + (lane >> 4) * 16);

    float acc[4][8][4];
#pragma unroll
    for (int a = 0; a < 4; a++)
#pragma unroll
        for (int b = 0; b < 8; b++)
#pragma unroll
            for (int c = 0; c < 4; c++) acc[a][b][c] = 0.f;

    auto issue = [&](int s) {
        int kk = s * 32;
        uint32_t Ab = sb + (s & 3) * ABYTES;
        uint32_t Bb = sb + STAGES * ABYTES + (s & 3) * BBYTES;
#pragma unroll
        for (int j = 0; j < 4; j++)
            CP16(Ab + adst + j * (32 * 80), asrc + (size_t)(32 * j) * IDIM + kk);
#pragma unroll
        for (int j = 0; j < 4; j++)
            CP16(Bb + bdst + j * (8 * BROWB), bsrc + (size_t)(kk + 8 * j) * HDIM);
    };

    issue(0); CP_COMMIT();
    issue(1); CP_COMMIT();
    issue(2); CP_COMMIT();

    const int NST = IDIM / 32;   // 88
    for (int s = 0; s < NST; s++) {
        CP_WAIT2();
        __syncthreads();
        if (s + 3 < NST) issue(s + 3);
        CP_COMMIT();
        uint32_t Ab = sb + (s & 3) * ABYTES;
        uint32_t Bb = sb + STAGES * ABYTES + (s & 3) * BBYTES;
#pragma unroll
        for (int ks = 0; ks < 2; ks++) {
            uint32_t af[4][4], bf[8][2];
#pragma unroll
            for (int mt = 0; mt < 4; mt++)
                LDSM_X4(af[mt][0], af[mt][1], af[mt][2], af[mt][3],
                        Ab + a_off + mt * 1280 + ks * 32);
#pragma unroll
            for (int p = 0; p < 4; p++) {
                uint32_t na = (uint32_t)(wn * 64 + p * 16);
                LDSM_X4T(bf[2 * p][0], bf[2 * p][1], bf[2 * p + 1][0], bf[2 * p + 1][1],
                         Bb + b_off + ks * (16 * BROWB) + na * 2);
            }
#pragma unroll
            for (int mt = 0; mt < 4; mt++)
#pragma unroll
                for (int nt = 0; nt < 8; nt++)
                    MMA_F16(acc[mt][nt], af[mt], bf[nt]);
        }
    }

#pragma unroll
    for (int mt = 0; mt < 4; mt++) {
        int r0 = m0 + wm * 64 + mt * 16 + qg;
#pragma unroll
        for (int nt = 0; nt < 8; nt++) {
            int c = n0 + wn * 64 + 8 * nt + 2 * qq;
            *(float2*)&g_y[((size_t)g * NTOK + r0) * HDIM + c] =
                make_float2(acc[mt][nt][0], acc[mt][nt][1]);
            *(float2*)&g_y[((size_t)g * NTOK + r0 + 8) * HDIM + c] =
                make_float2(acc[mt][nt][2], acc[mt][nt][3]);
        }
    }
}

// ---------------- combine ----------------
__global__ void k_combine(float* __restrict__ out) {
    int idx = blockIdx.x * blockDim.x + threadIdx.x;
    int t  = idx >> 8;
    int h4 = (idx & 255) << 2;
    if (t >= NTOK) return;

    int   e0 = g_te[2 * t + 0], p0 = g_tp[2 * t + 0];
    int   e1 = g_te[2 * t + 1], p1 = g_tp[2 * t + 1];
    float w0 = g_tw[2 * t + 0], w1 = g_tw[2 * t + 1];

    float4 yb = *(const float4*)&g_y[((size_t)NEXP * NTOK + t ) * HDIM + h4];
    float4 y0 = *(const float4*)&g_y[((size_t)e0   * NTOK + p0) * HDIM + h4];
    float4 y1 = *(const float4*)&g_y[((size_t)e1   * NTOK + p1) * HDIM + h4];

    float4 o;
    o.x = yb.x + w0 * y0.x + w1 * y1.x;
    o.y = yb.y + w0 * y0.y + w1 * y1.y;
    o.z = yb.z + w0 * y0.z + w1 * y1.z;
    o.w = yb.w + w0 * y0.w + w1 * y1.w;
    *(float4*)&out[(size_t)t * HDIM + h4] = o;
}

// ---------------- launch ----------------
extern "C" void kernel_launch(void* const* d_in, const int* in_sizes, int n_in,
                              void* d_out, int out_size) {
    const float* x        = (const float*)d_in[0];
    const float* gate_w   = (const float*)d_in[1];
    const float* base_wgu = (const float*)d_in[2];
    const float* base_wd  = (const float*)d_in[3];
    const float* exp_wgu  = (const float*)d_in[4];
    const float* exp_wd   = (const float*)d_in[5];
    float* out = (float*)d_out;

    cudaFuncSetAttribute(k_gemm1, cudaFuncAttributeMaxDynamicSharedMemorySize, SMEM_BYTES);
    cudaFuncSetAttribute(k_gemm2, cudaFuncAttributeMaxDynamicSharedMemorySize, SMEM_BYTES);

    k_init<<<1, 32>>>();
    k_cvt<<<(unsigned)((CVT_TOTAL + 255) / 256), 256>>>(x, base_wgu, base_wd, exp_wgu, exp_wd);
    k_router<<<(NTOK * 32) / 256, 256>>>(x, gate_w);
    k_gemm1<<<dim3(IDIM / 64, NTOK / 128, NGRP), 128, SMEM_BYTES>>>();
    k_gemm2<<<dim3(HDIM / 128, NTOK / 128, NGRP), 128, SMEM_BYTES>>>();
    k_combine<<<(NTOK * (HDIM / 4)) / 256, 256>>>(out);
}